// round 12
// baseline (speedup 1.0000x reference)
#include <cuda_runtime.h>
#include <cstdint>

// ---------------------------------------------------------------------------
// MultitaskLoss fused reduction — hybrid TMA + LDG pipeline (v4).
// TMA bulk copies carry ONLY ps [B,16] (57% of bytes) into a 4-stage smem
// ring; the naturally-coalesced small streams (pb/pt/tt/tb/lbl) go through
// plain LDG, issued BEFORE the mbar wait so their latency hides in it.
// Rationale: LDG-only plateaued at 4.5 TB/s, TMA-only at 5.1 TB/s -> both
// front-ends are individually capped; split the byte load across both.
// ---------------------------------------------------------------------------

#define NTHR   512
#define NBLK   148
#define TILE   512
#define STAGES 4
#define WARPS_PER_BLK (NTHR / 32)

// ---- smem layout: ps only ----
#define MBAR_OFF    0                 // 4 mbarriers * 8 B
#define STAGE_BASE  128
#define STAGE_BYTES (TILE * 64)       // 32768 (expect_tx)
#define SMEM_BYTES  (STAGE_BASE + STAGES * STAGE_BYTES)   // 131200

__device__ float g_part[5 * NBLK];
__device__ unsigned int g_count;      // zero-init; reset by last block

__device__ __forceinline__ float softplusf(float x) {
    return fmaxf(x, 0.0f) + __logf(1.0f + __expf(-fabsf(x)));
}

__device__ __forceinline__ float pick4(float4 v, int j) {
    float r = v.x;
    r = (j == 1) ? v.y : r;
    r = (j == 2) ? v.z : r;
    r = (j == 3) ? v.w : r;
    return r;
}

__device__ __forceinline__ void mbar_init(uint32_t mbar, uint32_t count) {
    asm volatile("mbarrier.init.shared.b64 [%0], %1;"
                 :: "r"(mbar), "r"(count) : "memory");
}
__device__ __forceinline__ void mbar_expect_tx(uint32_t mbar, uint32_t bytes) {
    asm volatile("mbarrier.arrive.expect_tx.shared.b64 _, [%0], %1;"
                 :: "r"(mbar), "r"(bytes) : "memory");
}
__device__ __forceinline__ void mbar_wait(uint32_t mbar, uint32_t parity) {
    asm volatile(
        "{\n\t"
        ".reg .pred P;\n\t"
        "WAIT_%=:\n\t"
        "mbarrier.try_wait.parity.acquire.cta.shared::cta.b64 P, [%0], %1, 0x989680;\n\t"
        "@P bra WAIT_DONE_%=;\n\t"
        "bra.uni WAIT_%=;\n\t"
        "WAIT_DONE_%=:\n\t"
        "}"
        :: "r"(mbar), "r"(parity) : "memory");
}
__device__ __forceinline__ void bulk_cp(uint32_t dst, const void* src,
                                        uint32_t bytes, uint32_t mbar) {
    asm volatile(
        "cp.async.bulk.shared::cta.global.mbarrier::complete_tx::bytes "
        "[%0], [%1], %2, [%3];"
        :: "r"(dst), "l"(src), "r"(bytes), "r"(mbar) : "memory");
}

// thread 0 only: arm barrier + issue the ps tile as one bulk copy
__device__ __forceinline__ void issue_tile(uint32_t st, uint32_t mbar,
                                           long tile, const char* ps)
{
    mbar_expect_tx(mbar, STAGE_BYTES);
    bulk_cp(st, ps + tile * (TILE * 64L), TILE * 64, mbar);
}

__global__ void __launch_bounds__(NTHR, 1)
mtl_hybrid_kernel(const float* __restrict__ pb,    // [B]    y_pred_binary
                  const float* __restrict__ pt,    // [B,4]  y_pred_type
                  const float* __restrict__ ps,    // [B,16] y_pred_source
                  const float* __restrict__ tb,    // [B]    y_true_binary
                  const float* __restrict__ tt,    // [B,4]  y_true_type
                  const int*   __restrict__ lbl,   // [B]    y_true_source
                  float* __restrict__ out,
                  int B)
{
    extern __shared__ char smem[];
    const uint32_t sb = (uint32_t)__cvta_generic_to_shared(smem);

    const int tid  = threadIdx.x;
    const int cta  = blockIdx.x;
    const int lane = tid & 31;
    const int rot  = (lane >> 1) & 3;          // ps chunk rotation (bank fix)
    const int ntiles = B / TILE;

    const char* psc = (const char*)ps;
    const float4* pt4 = (const float4*)pt;
    const float4* tt4 = (const float4*)tt;

    if (tid == 0) {
        #pragma unroll
        for (int s = 0; s < STAGES; s++)
            mbar_init(sb + MBAR_OFF + s * 8, 1);
        asm volatile("fence.proxy.async.shared::cta;" ::: "memory");
    }
    __syncthreads();

    // ---- prologue: fill the ring ----
    if (tid == 0) {
        #pragma unroll
        for (int p = 0; p < STAGES; p++) {
            long tile = cta + (long)NBLK * p;
            if (tile < ntiles)
                issue_tile(sb + STAGE_BASE + p * STAGE_BYTES,
                           sb + MBAR_OFF + p * 8, tile, psc);
        }
    }

    float s_b = 0.f, s_t = 0.f, s_ce = 0.f, s_ab = 0.f, s_ac = 0.f;

    long k = 0;
    for (long tile = cta; tile < ntiles; tile += NBLK, k++) {
        const int stage  = (int)(k & (STAGES - 1));
        const uint32_t parity = (uint32_t)((k >> 2) & 1);
        const uint32_t mbar = sb + MBAR_OFF + stage * 8;

        // ---- LDG small streams FIRST: latency hides under mbar wait ----
        const long i = tile * TILE + tid;
        float  xb = pb[i];
        float  yb = tb[i];
        float4 xt = pt4[i];
        float4 yt = tt4[i];
        int    l  = lbl[i];

        mbar_wait(mbar, parity);

        // ---- ps from smem, rotated chunks -> conflict-free LDS.128 ----
        const char* row = smem + STAGE_BASE + stage * STAGE_BYTES + tid * 64;
        float4 v0 = *(const float4*)(row + (((rot + 0) & 3) << 4));
        float4 v1 = *(const float4*)(row + (((rot + 1) & 3) << 4));
        float4 v2 = *(const float4*)(row + (((rot + 2) & 3) << 4));
        float4 v3 = *(const float4*)(row + (((rot + 3) & 3) << 4));

        // ---- release the stage: data is in registers ----
        __syncthreads();
        if (tid == 0) {
            long next = tile + (long)NBLK * STAGES;
            if (next < ntiles)
                issue_tile(sb + STAGE_BASE + stage * STAGE_BYTES, mbar,
                           next, psc);
        }

        // ---- FLOP chain overlaps the refill ----
        s_b += softplusf(xb) - yb * xb;
        s_t += (softplusf(xt.x) - yt.x * xt.x)
             + (softplusf(xt.y) - yt.y * xt.y)
             + (softplusf(xt.z) - yt.z * xt.z)
             + (softplusf(xt.w) - yt.w * xt.w);
        bool tc = (xt.x >= 0.f) | (xt.y >= 0.f) | (xt.z >= 0.f) | (xt.w >= 0.f);

        float m = fmaxf(
            fmaxf(fmaxf(fmaxf(v0.x, v0.y), fmaxf(v0.z, v0.w)),
                  fmaxf(fmaxf(v1.x, v1.y), fmaxf(v1.z, v1.w))),
            fmaxf(fmaxf(fmaxf(v2.x, v2.y), fmaxf(v2.z, v2.w)),
                  fmaxf(fmaxf(v3.x, v3.y), fmaxf(v3.z, v3.w))));

        float se = __expf(v0.x - m) + __expf(v0.y - m) + __expf(v0.z - m) + __expf(v0.w - m)
                 + __expf(v1.x - m) + __expf(v1.y - m) + __expf(v1.z - m) + __expf(v1.w - m)
                 + __expf(v2.x - m) + __expf(v2.y - m) + __expf(v2.z - m) + __expf(v2.w - m)
                 + __expf(v3.x - m) + __expf(v3.y - m) + __expf(v3.z - m) + __expf(v3.w - m);

        // label chunk: v[j] holds ps chunk (rot+j)&3  ->  j = (chunk - rot)&3
        int jj = ((l >> 2) - rot) & 3;
        float4 w = (jj & 2) ? ((jj & 1) ? v3 : v2) : ((jj & 1) ? v1 : v0);
        s_ce += m + __logf(se) - pick4(w, l & 3);

        // ps[0] lives in v[(0 - rot)&3].x
        int j0 = (-rot) & 3;
        float ax = (j0 & 2) ? ((j0 & 1) ? v3.x : v2.x)
                            : ((j0 & 1) ? v1.x : v0.x);

        bool bc = (xb >= 0.f);              // sigmoid(x) >= 0.5 <=> x >= 0
        bool sc = (ax < m);                 // argmax > 0 (first-occurrence)
        s_ab += (bc != tc) ? 1.f : 0.f;
        s_ac += (bc != sc) ? 1.f : 0.f;
    }

    // ---- remainder samples (B % TILE) — direct gmem, CTA 0 only ----
    if (cta == 0) {
        for (int i = ntiles * TILE + tid; i < B; i += NTHR) {
            float  xb = pb[i];
            float  yb = tb[i];
            float4 xt = pt4[i];
            float4 yt = tt4[i];
            s_b += softplusf(xb) - yb * xb;
            s_t += (softplusf(xt.x) - yt.x * xt.x)
                 + (softplusf(xt.y) - yt.y * xt.y)
                 + (softplusf(xt.z) - yt.z * xt.z)
                 + (softplusf(xt.w) - yt.w * xt.w);
            bool tc = (xt.x >= 0.f) | (xt.y >= 0.f) | (xt.z >= 0.f) | (xt.w >= 0.f);

            const float4* pr = (const float4*)(ps + 16L * i);
            float4 a = pr[0], b = pr[1], c = pr[2], d = pr[3];
            float m = fmaxf(
                fmaxf(fmaxf(fmaxf(a.x, a.y), fmaxf(a.z, a.w)),
                      fmaxf(fmaxf(b.x, b.y), fmaxf(b.z, b.w))),
                fmaxf(fmaxf(fmaxf(c.x, c.y), fmaxf(c.z, c.w)),
                      fmaxf(fmaxf(d.x, d.y), fmaxf(d.z, d.w))));
            float se = __expf(a.x-m)+__expf(a.y-m)+__expf(a.z-m)+__expf(a.w-m)
                     + __expf(b.x-m)+__expf(b.y-m)+__expf(b.z-m)+__expf(b.w-m)
                     + __expf(c.x-m)+__expf(c.y-m)+__expf(c.z-m)+__expf(c.w-m)
                     + __expf(d.x-m)+__expf(d.y-m)+__expf(d.z-m)+__expf(d.w-m);
            int l = lbl[i];
            float4 v = (l < 8) ? ((l < 4) ? a : b) : ((l < 12) ? c : d);
            s_ce += m + __logf(se) - pick4(v, l & 3);
            bool bc = (xb >= 0.f);
            bool sc = (a.x < m);
            s_ab += (bc != tc) ? 1.f : 0.f;
            s_ac += (bc != sc) ? 1.f : 0.f;
        }
    }

    // ---- block reduction ----
    #pragma unroll
    for (int o = 16; o; o >>= 1) {
        s_b  += __shfl_down_sync(0xffffffffu, s_b,  o);
        s_t  += __shfl_down_sync(0xffffffffu, s_t,  o);
        s_ce += __shfl_down_sync(0xffffffffu, s_ce, o);
        s_ab += __shfl_down_sync(0xffffffffu, s_ab, o);
        s_ac += __shfl_down_sync(0xffffffffu, s_ac, o);
    }

    __shared__ float red[5][WARPS_PER_BLK];
    int warp = tid >> 5;
    if (lane == 0) {
        red[0][warp] = s_b;  red[1][warp] = s_t;  red[2][warp] = s_ce;
        red[3][warp] = s_ab; red[4][warp] = s_ac;
    }
    __syncthreads();

    if (tid == 0) {
        float t0=0.f, t1=0.f, t2=0.f, t3=0.f, t4=0.f;
        #pragma unroll
        for (int j = 0; j < WARPS_PER_BLK; j++) {
            t0 += red[0][j]; t1 += red[1][j]; t2 += red[2][j];
            t3 += red[3][j]; t4 += red[4][j];
        }
        g_part[0 * NBLK + cta] = t0;
        g_part[1 * NBLK + cta] = t1;
        g_part[2 * NBLK + cta] = t2;
        g_part[3 * NBLK + cta] = t3;
        g_part[4 * NBLK + cta] = t4;
    }

    // ---- last-block finalize ----
    __shared__ bool is_last;
    if (tid == 0) {
        __threadfence();
        unsigned int done = atomicAdd(&g_count, 1u);
        is_last = (done == (unsigned int)(gridDim.x - 1));
    }
    __syncthreads();
    if (!is_last) return;

    __threadfence();

    if (tid < 32) {                        // 148 partials -> one warp
        double acc[5] = {0.0, 0.0, 0.0, 0.0, 0.0};
        for (int bx = tid; bx < NBLK; bx += 32) {
            #pragma unroll
            for (int q = 0; q < 5; q++)
                acc[q] += (double)g_part[q * NBLK + bx];
        }
        #pragma unroll
        for (int o = 16; o; o >>= 1) {
            #pragma unroll
            for (int q = 0; q < 5; q++)
                acc[q] += __shfl_down_sync(0xffffffffu, acc[q], o);
        }
        if (tid == 0) {
            double Bd = (double)B;
            double loss = acc[0] / Bd            // binary BCE mean
                        + acc[1] / (Bd * 4.0)    // type BCE mean over B*T
                        + acc[2] / Bd            // CE mean
                        + acc[3] / Bd            // cons_ab mean
                        + acc[4] / Bd;           // cons_ac mean
            out[0] = (float)loss;
            g_count = 0;                         // reset for next replay
        }
    }
}

extern "C" void kernel_launch(void* const* d_in, const int* in_sizes, int n_in,
                              void* d_out, int out_size)
{
    const float* pb  = (const float*)d_in[0];   // y_pred_binary  [B]
    const float* pt  = (const float*)d_in[1];   // y_pred_type    [B,4]
    const float* ps  = (const float*)d_in[2];   // y_pred_source  [B,16]
    const float* tb  = (const float*)d_in[3];   // y_true_binary  [B]
    const float* tt  = (const float*)d_in[4];   // y_true_type    [B,4]
    const int*   lbl = (const int*)  d_in[5];   // y_true_source  [B]
    float* out = (float*)d_out;

    int B = in_sizes[0];

    cudaFuncSetAttribute(mtl_hybrid_kernel,
                         cudaFuncAttributeMaxDynamicSharedMemorySize, SMEM_BYTES);
    mtl_hybrid_kernel<<<NBLK, NTHR, SMEM_BYTES>>>(pb, pt, ps, tb, tt, lbl, out, B);
}

// round 13
// speedup vs baseline: 1.0384x; 1.0384x over previous
#include <cuda_runtime.h>
#include <cstdint>

// ---------------------------------------------------------------------------
// MultitaskLoss fused reduction — hybrid TMA + LDG pipeline, v5.
// TMA bulk carries ps [B,16] into a 3-stage x 64KB smem ring; small coalesced
// streams (pb/pt/tt/tb/lbl) via LDG issued BEFORE the mbar wait.
// NEW vs R12: TILE=1024 with 2 samples/thread -> two independent FLOP chains
// per thread (2x ILP for the MUFU-heavy body) and half the per-sample
// pipeline overhead (waits/syncs/reissues).
// ---------------------------------------------------------------------------

#define NTHR   512
#define NBLK   148
#define TILE   1024
#define STAGES 3
#define WARPS_PER_BLK (NTHR / 32)

// ---- smem layout: ps only ----
#define MBAR_OFF    0                 // 3 mbarriers * 8 B
#define STAGE_BASE  128
#define STAGE_BYTES (TILE * 64)       // 65536 (expect_tx)
#define SMEM_BYTES  (STAGE_BASE + STAGES * STAGE_BYTES)   // 196736

__device__ float g_part[5 * NBLK];
__device__ unsigned int g_count;      // zero-init; reset by last block

__device__ __forceinline__ float softplusf(float x) {
    return fmaxf(x, 0.0f) + __logf(1.0f + __expf(-fabsf(x)));
}

__device__ __forceinline__ float pick4(float4 v, int j) {
    float r = v.x;
    r = (j == 1) ? v.y : r;
    r = (j == 2) ? v.z : r;
    r = (j == 3) ? v.w : r;
    return r;
}

__device__ __forceinline__ void mbar_init(uint32_t mbar, uint32_t count) {
    asm volatile("mbarrier.init.shared.b64 [%0], %1;"
                 :: "r"(mbar), "r"(count) : "memory");
}
__device__ __forceinline__ void mbar_expect_tx(uint32_t mbar, uint32_t bytes) {
    asm volatile("mbarrier.arrive.expect_tx.shared.b64 _, [%0], %1;"
                 :: "r"(mbar), "r"(bytes) : "memory");
}
__device__ __forceinline__ void mbar_wait(uint32_t mbar, uint32_t parity) {
    asm volatile(
        "{\n\t"
        ".reg .pred P;\n\t"
        "WAIT_%=:\n\t"
        "mbarrier.try_wait.parity.acquire.cta.shared::cta.b64 P, [%0], %1, 0x989680;\n\t"
        "@P bra WAIT_DONE_%=;\n\t"
        "bra.uni WAIT_%=;\n\t"
        "WAIT_DONE_%=:\n\t"
        "}"
        :: "r"(mbar), "r"(parity) : "memory");
}
__device__ __forceinline__ void bulk_cp(uint32_t dst, const void* src,
                                        uint32_t bytes, uint32_t mbar) {
    asm volatile(
        "cp.async.bulk.shared::cta.global.mbarrier::complete_tx::bytes "
        "[%0], [%1], %2, [%3];"
        :: "r"(dst), "l"(src), "r"(bytes), "r"(mbar) : "memory");
}

// thread 0 only: arm barrier + issue the ps tile as one bulk copy
__device__ __forceinline__ void issue_tile(uint32_t st, uint32_t mbar,
                                           long tile, const char* ps)
{
    mbar_expect_tx(mbar, STAGE_BYTES);
    bulk_cp(st, ps + tile * (TILE * 64L), TILE * 64, mbar);
}

// one sample's full loss contribution (ps already in v0..v3, rotated by rot)
__device__ __forceinline__ void accum_sample(
    float xb, float yb, float4 xt, float4 yt, int l,
    float4 v0, float4 v1, float4 v2, float4 v3, int rot,
    float& s_b, float& s_t, float& s_ce, float& s_ab, float& s_ac)
{
    s_b += softplusf(xb) - yb * xb;
    s_t += (softplusf(xt.x) - yt.x * xt.x)
         + (softplusf(xt.y) - yt.y * xt.y)
         + (softplusf(xt.z) - yt.z * xt.z)
         + (softplusf(xt.w) - yt.w * xt.w);
    bool tc = (xt.x >= 0.f) | (xt.y >= 0.f) | (xt.z >= 0.f) | (xt.w >= 0.f);

    float m = fmaxf(
        fmaxf(fmaxf(fmaxf(v0.x, v0.y), fmaxf(v0.z, v0.w)),
              fmaxf(fmaxf(v1.x, v1.y), fmaxf(v1.z, v1.w))),
        fmaxf(fmaxf(fmaxf(v2.x, v2.y), fmaxf(v2.z, v2.w)),
              fmaxf(fmaxf(v3.x, v3.y), fmaxf(v3.z, v3.w))));

    float se = __expf(v0.x - m) + __expf(v0.y - m) + __expf(v0.z - m) + __expf(v0.w - m)
             + __expf(v1.x - m) + __expf(v1.y - m) + __expf(v1.z - m) + __expf(v1.w - m)
             + __expf(v2.x - m) + __expf(v2.y - m) + __expf(v2.z - m) + __expf(v2.w - m)
             + __expf(v3.x - m) + __expf(v3.y - m) + __expf(v3.z - m) + __expf(v3.w - m);

    // label chunk: v[j] holds ps chunk (rot+j)&3  ->  j = (chunk - rot)&3
    int jj = ((l >> 2) - rot) & 3;
    float4 w = (jj & 2) ? ((jj & 1) ? v3 : v2) : ((jj & 1) ? v1 : v0);
    s_ce += m + __logf(se) - pick4(w, l & 3);

    // ps[0] lives in v[(0 - rot)&3].x
    int j0 = (-rot) & 3;
    float ax = (j0 & 2) ? ((j0 & 1) ? v3.x : v2.x)
                        : ((j0 & 1) ? v1.x : v0.x);

    bool bc = (xb >= 0.f);              // sigmoid(x) >= 0.5 <=> x >= 0
    bool sc = (ax < m);                 // argmax > 0 (first-occurrence)
    s_ab += (bc != tc) ? 1.f : 0.f;
    s_ac += (bc != sc) ? 1.f : 0.f;
}

__global__ void __launch_bounds__(NTHR, 1)
mtl_hybrid2_kernel(const float* __restrict__ pb,    // [B]    y_pred_binary
                   const float* __restrict__ pt,    // [B,4]  y_pred_type
                   const float* __restrict__ ps,    // [B,16] y_pred_source
                   const float* __restrict__ tb,    // [B]    y_true_binary
                   const float* __restrict__ tt,    // [B,4]  y_true_type
                   const int*   __restrict__ lbl,   // [B]    y_true_source
                   float* __restrict__ out,
                   int B)
{
    extern __shared__ char smem[];
    const uint32_t sb = (uint32_t)__cvta_generic_to_shared(smem);

    const int tid  = threadIdx.x;
    const int cta  = blockIdx.x;
    const int lane = tid & 31;
    const int rot  = (lane >> 1) & 3;          // ps chunk rotation (bank fix)
    const int ntiles = B / TILE;

    const char* psc = (const char*)ps;
    const float4* pt4 = (const float4*)pt;
    const float4* tt4 = (const float4*)tt;

    if (tid == 0) {
        #pragma unroll
        for (int s = 0; s < STAGES; s++)
            mbar_init(sb + MBAR_OFF + s * 8, 1);
        asm volatile("fence.proxy.async.shared::cta;" ::: "memory");
    }
    __syncthreads();

    // ---- prologue: fill the ring ----
    if (tid == 0) {
        #pragma unroll
        for (int p = 0; p < STAGES; p++) {
            long tile = cta + (long)NBLK * p;
            if (tile < ntiles)
                issue_tile(sb + STAGE_BASE + p * STAGE_BYTES,
                           sb + MBAR_OFF + p * 8, tile, psc);
        }
    }

    float s_b = 0.f, s_t = 0.f, s_ce = 0.f, s_ab = 0.f, s_ac = 0.f;

    int stage = 0;
    uint32_t phase = 0;
    for (long tile = cta; tile < ntiles; tile += NBLK) {
        const uint32_t mbar = sb + MBAR_OFF + stage * 8;

        // ---- LDG small streams FIRST: latency hides under mbar wait ----
        const long i0 = tile * TILE + tid;
        const long i1 = i0 + NTHR;
        float  xb0 = pb[i0],  xb1 = pb[i1];
        float  yb0 = tb[i0],  yb1 = tb[i1];
        float4 xt0 = pt4[i0], xt1 = pt4[i1];
        float4 yt0 = tt4[i0], yt1 = tt4[i1];
        int    l0  = lbl[i0], l1  = lbl[i1];

        mbar_wait(mbar, phase);

        // ---- ps from smem, rotated chunks -> conflict-free LDS.128 ----
        const char* base = smem + STAGE_BASE + stage * STAGE_BYTES;
        const char* rowA = base + tid * 64;
        const char* rowB = base + (tid + NTHR) * 64;
        float4 a0 = *(const float4*)(rowA + (((rot + 0) & 3) << 4));
        float4 a1 = *(const float4*)(rowA + (((rot + 1) & 3) << 4));
        float4 a2 = *(const float4*)(rowA + (((rot + 2) & 3) << 4));
        float4 a3 = *(const float4*)(rowA + (((rot + 3) & 3) << 4));
        float4 b0 = *(const float4*)(rowB + (((rot + 0) & 3) << 4));
        float4 b1 = *(const float4*)(rowB + (((rot + 1) & 3) << 4));
        float4 b2 = *(const float4*)(rowB + (((rot + 2) & 3) << 4));
        float4 b3 = *(const float4*)(rowB + (((rot + 3) & 3) << 4));

        // ---- release the stage: data is in registers ----
        __syncthreads();
        if (tid == 0) {
            long next = tile + (long)NBLK * STAGES;
            if (next < ntiles)
                issue_tile(sb + STAGE_BASE + stage * STAGE_BYTES, mbar,
                           next, psc);
        }

        // ---- two independent FLOP chains overlap the refill ----
        accum_sample(xb0, yb0, xt0, yt0, l0, a0, a1, a2, a3, rot,
                     s_b, s_t, s_ce, s_ab, s_ac);
        accum_sample(xb1, yb1, xt1, yt1, l1, b0, b1, b2, b3, rot,
                     s_b, s_t, s_ce, s_ab, s_ac);

        if (++stage == STAGES) { stage = 0; phase ^= 1u; }
    }

    // ---- remainder samples (B % TILE) — direct gmem, CTA 0 only ----
    if (cta == 0) {
        for (int i = ntiles * TILE + tid; i < B; i += NTHR) {
            float  xb = pb[i];
            float  yb = tb[i];
            float4 xt = pt4[i];
            float4 yt = tt4[i];
            const float4* pr = (const float4*)(ps + 16L * i);
            float4 a = pr[0], b = pr[1], c = pr[2], d = pr[3];
            accum_sample(xb, yb, xt, yt, lbl[i], a, b, c, d, 0,
                         s_b, s_t, s_ce, s_ab, s_ac);
        }
    }

    // ---- block reduction ----
    #pragma unroll
    for (int o = 16; o; o >>= 1) {
        s_b  += __shfl_down_sync(0xffffffffu, s_b,  o);
        s_t  += __shfl_down_sync(0xffffffffu, s_t,  o);
        s_ce += __shfl_down_sync(0xffffffffu, s_ce, o);
        s_ab += __shfl_down_sync(0xffffffffu, s_ab, o);
        s_ac += __shfl_down_sync(0xffffffffu, s_ac, o);
    }

    __shared__ float red[5][WARPS_PER_BLK];
    int warp = tid >> 5;
    if (lane == 0) {
        red[0][warp] = s_b;  red[1][warp] = s_t;  red[2][warp] = s_ce;
        red[3][warp] = s_ab; red[4][warp] = s_ac;
    }
    __syncthreads();

    if (tid == 0) {
        float t0=0.f, t1=0.f, t2=0.f, t3=0.f, t4=0.f;
        #pragma unroll
        for (int j = 0; j < WARPS_PER_BLK; j++) {
            t0 += red[0][j]; t1 += red[1][j]; t2 += red[2][j];
            t3 += red[3][j]; t4 += red[4][j];
        }
        g_part[0 * NBLK + cta] = t0;
        g_part[1 * NBLK + cta] = t1;
        g_part[2 * NBLK + cta] = t2;
        g_part[3 * NBLK + cta] = t3;
        g_part[4 * NBLK + cta] = t4;
    }

    // ---- last-block finalize ----
    __shared__ bool is_last;
    if (tid == 0) {
        __threadfence();
        unsigned int done = atomicAdd(&g_count, 1u);
        is_last = (done == (unsigned int)(gridDim.x - 1));
    }
    __syncthreads();
    if (!is_last) return;

    __threadfence();

    if (tid < 32) {                        // 148 partials -> one warp
        double acc[5] = {0.0, 0.0, 0.0, 0.0, 0.0};
        for (int bx = tid; bx < NBLK; bx += 32) {
            #pragma unroll
            for (int q = 0; q < 5; q++)
                acc[q] += (double)g_part[q * NBLK + bx];
        }
        #pragma unroll
        for (int o = 16; o; o >>= 1) {
            #pragma unroll
            for (int q = 0; q < 5; q++)
                acc[q] += __shfl_down_sync(0xffffffffu, acc[q], o);
        }
        if (tid == 0) {
            double Bd = (double)B;
            double loss = acc[0] / Bd            // binary BCE mean
                        + acc[1] / (Bd * 4.0)    // type BCE mean over B*T
                        + acc[2] / Bd            // CE mean
                        + acc[3] / Bd            // cons_ab mean
                        + acc[4] / Bd;           // cons_ac mean
            out[0] = (float)loss;
            g_count = 0;                         // reset for next replay
        }
    }
}

extern "C" void kernel_launch(void* const* d_in, const int* in_sizes, int n_in,
                              void* d_out, int out_size)
{
    const float* pb  = (const float*)d_in[0];   // y_pred_binary  [B]
    const float* pt  = (const float*)d_in[1];   // y_pred_type    [B,4]
    const float* ps  = (const float*)d_in[2];   // y_pred_source  [B,16]
    const float* tb  = (const float*)d_in[3];   // y_true_binary  [B]
    const float* tt  = (const float*)d_in[4];   // y_true_type    [B,4]
    const int*   lbl = (const int*)  d_in[5];   // y_true_source  [B]
    float* out = (float*)d_out;

    int B = in_sizes[0];

    cudaFuncSetAttribute(mtl_hybrid2_kernel,
                         cudaFuncAttributeMaxDynamicSharedMemorySize, SMEM_BYTES);
    mtl_hybrid2_kernel<<<NBLK, NTHR, SMEM_BYTES>>>(pb, pt, ps, tb, tt, lbl, out, B);
}

// round 15
// speedup vs baseline: 1.0902x; 1.0499x over previous
#include <cuda_runtime.h>
#include <cstdint>

// ---------------------------------------------------------------------------
// MultitaskLoss fused reduction — hybrid TMA + LDG pipeline, v6b.
// R13 skeleton (TMA carries ps into 3x64KB ring; LDG small streams before the
// mbar wait; TILE=1024, 2 samples/thread) + algebraic compute reduction:
//   * 6 logf/sample -> 2 log2f/sample via log-product fusion
//     (binary-BCE log + CE log fused; 4 type-BCE logs fused, 1/4 weight
//      applied at finalize since type-BCE is a mean over 4B)
//   * exp(v-m) -> ex2(fma(v, log2e, -m*log2e)) : FFMA+MUFU per term
//     (ex2 via inline PTX — __exp2f is not a CUDA intrinsic)
// Accumulators: s_lin (all linear terms, type weighted 1/4), s_l2bc, s_l2t,
// s_ab, s_ac. loss = (s_lin + ln2*(s_l2bc + 0.25*s_l2t) + s_ab + s_ac)/B.
// ---------------------------------------------------------------------------

#define NTHR   512
#define NBLK   148
#define TILE   1024
#define STAGES 3
#define WARPS_PER_BLK (NTHR / 32)

#define L2E 1.4426950408889634f      // log2(e)

// ---- smem layout: ps only ----
#define MBAR_OFF    0                 // 3 mbarriers * 8 B
#define STAGE_BASE  128
#define STAGE_BYTES (TILE * 64)       // 65536 (expect_tx)
#define SMEM_BYTES  (STAGE_BASE + STAGES * STAGE_BYTES)   // 196736

__device__ float g_part[5 * NBLK];
__device__ unsigned int g_count;      // zero-init; reset by last block

__device__ __forceinline__ float ex2f(float x) {          // raw MUFU EX2
    float r;
    asm("ex2.approx.ftz.f32 %0, %1;" : "=f"(r) : "f"(x));
    return r;
}

__device__ __forceinline__ float pick4(float4 v, int j) {
    float r = v.x;
    r = (j == 1) ? v.y : r;
    r = (j == 2) ? v.z : r;
    r = (j == 3) ? v.w : r;
    return r;
}

__device__ __forceinline__ void mbar_init(uint32_t mbar, uint32_t count) {
    asm volatile("mbarrier.init.shared.b64 [%0], %1;"
                 :: "r"(mbar), "r"(count) : "memory");
}
__device__ __forceinline__ void mbar_expect_tx(uint32_t mbar, uint32_t bytes) {
    asm volatile("mbarrier.arrive.expect_tx.shared.b64 _, [%0], %1;"
                 :: "r"(mbar), "r"(bytes) : "memory");
}
__device__ __forceinline__ void mbar_wait(uint32_t mbar, uint32_t parity) {
    asm volatile(
        "{\n\t"
        ".reg .pred P;\n\t"
        "WAIT_%=:\n\t"
        "mbarrier.try_wait.parity.acquire.cta.shared::cta.b64 P, [%0], %1, 0x989680;\n\t"
        "@P bra WAIT_DONE_%=;\n\t"
        "bra.uni WAIT_%=;\n\t"
        "WAIT_DONE_%=:\n\t"
        "}"
        :: "r"(mbar), "r"(parity) : "memory");
}
__device__ __forceinline__ void bulk_cp(uint32_t dst, const void* src,
                                        uint32_t bytes, uint32_t mbar) {
    asm volatile(
        "cp.async.bulk.shared::cta.global.mbarrier::complete_tx::bytes "
        "[%0], [%1], %2, [%3];"
        :: "r"(dst), "l"(src), "r"(bytes), "r"(mbar) : "memory");
}

// thread 0 only: arm barrier + issue the ps tile as one bulk copy
__device__ __forceinline__ void issue_tile(uint32_t st, uint32_t mbar,
                                           long tile, const char* ps)
{
    mbar_expect_tx(mbar, STAGE_BYTES);
    bulk_cp(st, ps + tile * (TILE * 64L), TILE * 64, mbar);
}

// one sample's contribution with fused logs / exp2 arithmetic
__device__ __forceinline__ void accum_sample(
    float xb, float yb, float4 xt, float4 yt, int l,
    float4 v0, float4 v1, float4 v2, float4 v3, int rot,
    float& s_lin, float& s_l2bc, float& s_l2t, float& s_ab, float& s_ac)
{
    // ---- binary BCE linear + (1 + e^-|xb|) ----
    float lin = fmaxf(xb, 0.f) - yb * xb;
    float pb_ = 1.0f + ex2f(-L2E * fabsf(xb));

    // ---- type BCE: linear terms (weight 1/4) + product of (1+e^-|x|) ----
    float tlin = (fmaxf(xt.x, 0.f) - yt.x * xt.x)
               + (fmaxf(xt.y, 0.f) - yt.y * xt.y)
               + (fmaxf(xt.z, 0.f) - yt.z * xt.z)
               + (fmaxf(xt.w, 0.f) - yt.w * xt.w);
    lin += 0.25f * tlin;
    float q0 = 1.0f + ex2f(-L2E * fabsf(xt.x));
    float q1 = 1.0f + ex2f(-L2E * fabsf(xt.y));
    float q2 = 1.0f + ex2f(-L2E * fabsf(xt.z));
    float q3 = 1.0f + ex2f(-L2E * fabsf(xt.w));
    bool tc = (xt.x >= 0.f) | (xt.y >= 0.f) | (xt.z >= 0.f) | (xt.w >= 0.f);

    // ---- CE: max, exp2-sum, label pick ----
    float m = fmaxf(
        fmaxf(fmaxf(fmaxf(v0.x, v0.y), fmaxf(v0.z, v0.w)),
              fmaxf(fmaxf(v1.x, v1.y), fmaxf(v1.z, v1.w))),
        fmaxf(fmaxf(fmaxf(v2.x, v2.y), fmaxf(v2.z, v2.w)),
              fmaxf(fmaxf(v3.x, v3.y), fmaxf(v3.z, v3.w))));
    float mm = m * L2E;

    float se = ex2f(__fmaf_rn(v0.x, L2E, -mm)) + ex2f(__fmaf_rn(v0.y, L2E, -mm))
             + ex2f(__fmaf_rn(v0.z, L2E, -mm)) + ex2f(__fmaf_rn(v0.w, L2E, -mm))
             + ex2f(__fmaf_rn(v1.x, L2E, -mm)) + ex2f(__fmaf_rn(v1.y, L2E, -mm))
             + ex2f(__fmaf_rn(v1.z, L2E, -mm)) + ex2f(__fmaf_rn(v1.w, L2E, -mm))
             + ex2f(__fmaf_rn(v2.x, L2E, -mm)) + ex2f(__fmaf_rn(v2.y, L2E, -mm))
             + ex2f(__fmaf_rn(v2.z, L2E, -mm)) + ex2f(__fmaf_rn(v2.w, L2E, -mm))
             + ex2f(__fmaf_rn(v3.x, L2E, -mm)) + ex2f(__fmaf_rn(v3.y, L2E, -mm))
             + ex2f(__fmaf_rn(v3.z, L2E, -mm)) + ex2f(__fmaf_rn(v3.w, L2E, -mm));

    // label chunk: v[j] holds ps chunk (rot+j)&3  ->  j = (chunk - rot)&3
    int jj = ((l >> 2) - rot) & 3;
    float4 w = (jj & 2) ? ((jj & 1) ? v3 : v2) : ((jj & 1) ? v1 : v0);
    lin += m - pick4(w, l & 3);

    // ---- fused logs: 2 LG2 per sample ----
    s_l2bc += __log2f(pb_ * se);
    s_l2t  += __log2f(((q0 * q1) * (q2 * q3)));
    s_lin  += lin;

    // ps[0] lives in v[(0 - rot)&3].x
    int j0 = (-rot) & 3;
    float ax = (j0 & 2) ? ((j0 & 1) ? v3.x : v2.x)
                        : ((j0 & 1) ? v1.x : v0.x);

    bool bc = (xb >= 0.f);              // sigmoid(x) >= 0.5 <=> x >= 0
    bool sc = (ax < m);                 // argmax > 0 (first-occurrence)
    s_ab += (bc != tc) ? 1.f : 0.f;
    s_ac += (bc != sc) ? 1.f : 0.f;
}

__global__ void __launch_bounds__(NTHR, 1)
mtl_v6_kernel(const float* __restrict__ pb,    // [B]    y_pred_binary
              const float* __restrict__ pt,    // [B,4]  y_pred_type
              const float* __restrict__ ps,    // [B,16] y_pred_source
              const float* __restrict__ tb,    // [B]    y_true_binary
              const float* __restrict__ tt,    // [B,4]  y_true_type
              const int*   __restrict__ lbl,   // [B]    y_true_source
              float* __restrict__ out,
              int B)
{
    extern __shared__ char smem[];
    const uint32_t sb = (uint32_t)__cvta_generic_to_shared(smem);

    const int tid  = threadIdx.x;
    const int cta  = blockIdx.x;
    const int lane = tid & 31;
    const int rot  = (lane >> 1) & 3;          // ps chunk rotation (bank fix)
    const int ntiles = B / TILE;

    const char* psc = (const char*)ps;
    const float4* pt4 = (const float4*)pt;
    const float4* tt4 = (const float4*)tt;

    if (tid == 0) {
        #pragma unroll
        for (int s = 0; s < STAGES; s++)
            mbar_init(sb + MBAR_OFF + s * 8, 1);
        asm volatile("fence.proxy.async.shared::cta;" ::: "memory");
    }
    __syncthreads();

    // ---- prologue: fill the ring ----
    if (tid == 0) {
        #pragma unroll
        for (int p = 0; p < STAGES; p++) {
            long tile = cta + (long)NBLK * p;
            if (tile < ntiles)
                issue_tile(sb + STAGE_BASE + p * STAGE_BYTES,
                           sb + MBAR_OFF + p * 8, tile, psc);
        }
    }

    float s_lin = 0.f, s_l2bc = 0.f, s_l2t = 0.f, s_ab = 0.f, s_ac = 0.f;

    int stage = 0;
    uint32_t phase = 0;
    for (long tile = cta; tile < ntiles; tile += NBLK) {
        const uint32_t mbar = sb + MBAR_OFF + stage * 8;

        // ---- LDG small streams FIRST: latency hides under mbar wait ----
        const long i0 = tile * TILE + tid;
        const long i1 = i0 + NTHR;
        float  xb0 = pb[i0],  xb1 = pb[i1];
        float  yb0 = tb[i0],  yb1 = tb[i1];
        float4 xt0 = pt4[i0], xt1 = pt4[i1];
        float4 yt0 = tt4[i0], yt1 = tt4[i1];
        int    l0  = lbl[i0], l1  = lbl[i1];

        mbar_wait(mbar, phase);

        // ---- ps from smem, rotated chunks -> conflict-free LDS.128 ----
        const char* base = smem + STAGE_BASE + stage * STAGE_BYTES;
        const char* rowA = base + tid * 64;
        const char* rowB = base + (tid + NTHR) * 64;
        float4 a0 = *(const float4*)(rowA + (((rot + 0) & 3) << 4));
        float4 a1 = *(const float4*)(rowA + (((rot + 1) & 3) << 4));
        float4 a2 = *(const float4*)(rowA + (((rot + 2) & 3) << 4));
        float4 a3 = *(const float4*)(rowA + (((rot + 3) & 3) << 4));
        float4 b0 = *(const float4*)(rowB + (((rot + 0) & 3) << 4));
        float4 b1 = *(const float4*)(rowB + (((rot + 1) & 3) << 4));
        float4 b2 = *(const float4*)(rowB + (((rot + 2) & 3) << 4));
        float4 b3 = *(const float4*)(rowB + (((rot + 3) & 3) << 4));

        // ---- release the stage: data is in registers ----
        __syncthreads();
        if (tid == 0) {
            long next = tile + (long)NBLK * STAGES;
            if (next < ntiles)
                issue_tile(sb + STAGE_BASE + stage * STAGE_BYTES, mbar,
                           next, psc);
        }

        // ---- two independent FLOP chains overlap the refill ----
        accum_sample(xb0, yb0, xt0, yt0, l0, a0, a1, a2, a3, rot,
                     s_lin, s_l2bc, s_l2t, s_ab, s_ac);
        accum_sample(xb1, yb1, xt1, yt1, l1, b0, b1, b2, b3, rot,
                     s_lin, s_l2bc, s_l2t, s_ab, s_ac);

        if (++stage == STAGES) { stage = 0; phase ^= 1u; }
    }

    // ---- remainder samples (B % TILE) — direct gmem, CTA 0 only ----
    if (cta == 0) {
        for (int i = ntiles * TILE + tid; i < B; i += NTHR) {
            float  xb = pb[i];
            float  yb = tb[i];
            float4 xt = pt4[i];
            float4 yt = tt4[i];
            const float4* pr = (const float4*)(ps + 16L * i);
            float4 a = pr[0], b = pr[1], c = pr[2], d = pr[3];
            accum_sample(xb, yb, xt, yt, lbl[i], a, b, c, d, 0,
                         s_lin, s_l2bc, s_l2t, s_ab, s_ac);
        }
    }

    // ---- block reduction ----
    #pragma unroll
    for (int o = 16; o; o >>= 1) {
        s_lin  += __shfl_down_sync(0xffffffffu, s_lin,  o);
        s_l2bc += __shfl_down_sync(0xffffffffu, s_l2bc, o);
        s_l2t  += __shfl_down_sync(0xffffffffu, s_l2t,  o);
        s_ab   += __shfl_down_sync(0xffffffffu, s_ab,   o);
        s_ac   += __shfl_down_sync(0xffffffffu, s_ac,   o);
    }

    __shared__ float red[5][WARPS_PER_BLK];
    int warp = tid >> 5;
    if (lane == 0) {
        red[0][warp] = s_lin;  red[1][warp] = s_l2bc; red[2][warp] = s_l2t;
        red[3][warp] = s_ab;   red[4][warp] = s_ac;
    }
    __syncthreads();

    if (tid == 0) {
        float t0=0.f, t1=0.f, t2=0.f, t3=0.f, t4=0.f;
        #pragma unroll
        for (int j = 0; j < WARPS_PER_BLK; j++) {
            t0 += red[0][j]; t1 += red[1][j]; t2 += red[2][j];
            t3 += red[3][j]; t4 += red[4][j];
        }
        g_part[0 * NBLK + cta] = t0;
        g_part[1 * NBLK + cta] = t1;
        g_part[2 * NBLK + cta] = t2;
        g_part[3 * NBLK + cta] = t3;
        g_part[4 * NBLK + cta] = t4;
    }

    // ---- last-block finalize ----
    __shared__ bool is_last;
    if (tid == 0) {
        __threadfence();
        unsigned int done = atomicAdd(&g_count, 1u);
        is_last = (done == (unsigned int)(gridDim.x - 1));
    }
    __syncthreads();
    if (!is_last) return;

    __threadfence();

    if (tid < 32) {                        // 148 partials -> one warp
        double acc[5] = {0.0, 0.0, 0.0, 0.0, 0.0};
        for (int bx = tid; bx < NBLK; bx += 32) {
            #pragma unroll
            for (int q = 0; q < 5; q++)
                acc[q] += (double)g_part[q * NBLK + bx];
        }
        #pragma unroll
        for (int o = 16; o; o >>= 1) {
            #pragma unroll
            for (int q = 0; q < 5; q++)
                acc[q] += __shfl_down_sync(0xffffffffu, acc[q], o);
        }
        if (tid == 0) {
            const double LN2 = 0.6931471805599453;
            double Bd = (double)B;
            // acc[0]=lin (type terms pre-weighted 1/4), acc[1]=log2(bce_b*se),
            // acc[2]=log2(type products), acc[3]=ab, acc[4]=ac
            double loss = (acc[0]
                         + LN2 * (acc[1] + 0.25 * acc[2])
                         + acc[3] + acc[4]) / Bd;
            out[0] = (float)loss;
            g_count = 0;                         // reset for next replay
        }
    }
}

extern "C" void kernel_launch(void* const* d_in, const int* in_sizes, int n_in,
                              void* d_out, int out_size)
{
    const float* pb  = (const float*)d_in[0];   // y_pred_binary  [B]
    const float* pt  = (const float*)d_in[1];   // y_pred_type    [B,4]
    const float* ps  = (const float*)d_in[2];   // y_pred_source  [B,16]
    const float* tb  = (const float*)d_in[3];   // y_true_binary  [B]
    const float* tt  = (const float*)d_in[4];   // y_true_type    [B,4]
    const int*   lbl = (const int*)  d_in[5];   // y_true_source  [B]
    float* out = (float*)d_out;

    int B = in_sizes[0];

    cudaFuncSetAttribute(mtl_v6_kernel,
                         cudaFuncAttributeMaxDynamicSharedMemorySize, SMEM_BYTES);
    mtl_v6_kernel<<<NBLK, NTHR, SMEM_BYTES>>>(pb, pt, ps, tb, tt, lbl, out, B);
}